// round 2
// baseline (speedup 1.0000x reference)
#include <cuda_runtime.h>

// SPConv fused GNN kernel, fp32 SIMT baseline (R2: edge_index dtype fix).

#define TPB 256
#define TE 64        // edges (or nodes) per tile
#define PITCH 65     // smem row pitch (conflict-free: 65 % 32 == 1)

__device__ float g_cnt[65536];   // per-node edge counts (N = 50000)
__device__ int g_idx64;          // 1 if edge_index is int64, 0 if int32

// Detect edge_index dtype: true-int64 indices (< N) always have zero high
// words; packed int32 pairs have random nonzero high words.
__global__ void detect_kernel(const unsigned long long* __restrict__ ei) {
    if (threadIdx.x == 0 && blockIdx.x == 0) {
        int is64 = 1;
        for (int i = 0; i < 64; ++i)
            if ((ei[i] >> 32) != 0ull) { is64 = 0; break; }
        g_idx64 = is64;
    }
}

// Register-tiled GEMM chunk: acc[2][8] += H[k][e0..e0+7] * W[k][c0..c0+1]
__device__ __forceinline__ void gemm_chunk(const float* __restrict__ H,
                                           const float* __restrict__ W,
                                           int K, int c0, int e0,
                                           float acc[2][8]) {
#pragma unroll 8
    for (int k = 0; k < K; ++k) {
        float2 w = *reinterpret_cast<const float2*>(W + k * 64 + c0);
        const float* hr = H + k * PITCH + e0;
#pragma unroll
        for (int j = 0; j < 8; ++j) {
            float h = hr[j];
            acc[0][j] = fmaf(w.x, h, acc[0][j]);
            acc[1][j] = fmaf(w.y, h, acc[1][j]);
        }
    }
}

__global__ void zero_kernel(float* __restrict__ sums, int total, int n) {
    int i = blockIdx.x * blockDim.x + threadIdx.x;
    if (i < total) sums[i] = 0.0f;
    if (i < n) g_cnt[i] = 0.0f;
}

// Shared memory layout (floats) for edge_kernel:
//      0 : Wm1 [192][64]   12288
//  12288 : We2 [64][64]     4096
//  16384 : Wm2 [64][64]     4096
//  20480 : We1 [3][64]       192
//  20672 : be1 | 20736 : be2 | 20800 : bm1 | 20864 : bm2   (64 each)
//  20928 : delta [3][PITCH]  196 (padded)
//  21124 : Zs [64][PITCH]   4160
//  25284 : Zd               4160
//  29444 : Ef               4160
//  33604 : Buf              4160
//  37764 : src/dst ints     (128 ints)
__global__ __launch_bounds__(TPB) void edge_kernel(
    const float* __restrict__ z, const float* __restrict__ cent,
    const void* __restrict__ ei_raw,
    const float* __restrict__ We1, const float* __restrict__ be1,
    const float* __restrict__ We2, const float* __restrict__ be2,
    const float* __restrict__ Wm1, const float* __restrict__ bm1,
    const float* __restrict__ Wm2, const float* __restrict__ bm2,
    float* __restrict__ sums, int E, int N, int ntiles) {
    extern __shared__ float sm[];
    float* sWm1 = sm;
    float* sWe2 = sm + 12288;
    float* sWm2 = sm + 16384;
    float* sWe1 = sm + 20480;
    float* sbe1 = sm + 20672;
    float* sbe2 = sm + 20736;
    float* sbm1 = sm + 20800;
    float* sbm2 = sm + 20864;
    float* sDelta = sm + 20928;
    float* sZs = sm + 21124;
    float* sZd = sm + 25284;
    float* sEf = sm + 29444;
    float* sBuf = sm + 33604;
    int* sSrc = (int*)(sm + 37764);
    int* sDst = sSrc + TE;

    const int tid = threadIdx.x;
    const int idx64 = g_idx64;
    const long long* ei64 = (const long long*)ei_raw;
    const int* ei32 = (const int*)ei_raw;

    // Stage all weights once per block.
    for (int i = tid; i < 12288; i += TPB) sWm1[i] = Wm1[i];
    for (int i = tid; i < 4096; i += TPB) { sWe2[i] = We2[i]; sWm2[i] = Wm2[i]; }
    if (tid < 192) sWe1[tid] = We1[tid];
    if (tid < 64) {
        sbe1[tid] = be1[tid]; sbe2[tid] = be2[tid];
        sbm1[tid] = bm1[tid]; sbm2[tid] = bm2[tid];
    }
    __syncthreads();

    const int cg = tid >> 3, eg = tid & 7;
    const int c0 = cg * 2, e0 = eg * 8;

    for (int tile = blockIdx.x; tile < ntiles; tile += gridDim.x) {
        const int base = tile * TE;

        if (tid < TE) {
            int e = base + tid;
            if (e < E) {
                int s, d;
                if (idx64) {
                    s = (int)ei64[e];
                    d = (int)ei64[(size_t)E + e];
                } else {
                    s = ei32[e];
                    d = ei32[(size_t)E + e];
                }
                // safety clamp: wrong values -> wrong answer, not a crash
                if (s < 0 || s >= N) s = 0;
                if (d < 0 || d >= N) d = 0;
                sSrc[tid] = s;
                sDst[tid] = d;
            } else {
                sSrc[tid] = 0;
                sDst[tid] = -1;
            }
        }
        __syncthreads();

        // delta = centroids[dst] - centroids[src]
        if (tid < 3 * TE) {
            int e = tid & 63, comp = tid >> 6;
            int s = sSrc[e], d = sDst[e];
            int ds = (d < 0) ? s : d;
            sDelta[comp * PITCH + e] =
                cent[(size_t)ds * 3 + comp] - cent[(size_t)s * 3 + comp];
        }
        // Gather z[src], z[dst] -> transposed smem
        for (int i = tid; i < TE * 64; i += TPB) {
            int e = i >> 6, k = i & 63;
            int s = sSrc[e], d = sDst[e];
            int ds = (d < 0) ? s : d;
            sZs[k * PITCH + e] = z[(size_t)s * 64 + k];
            sZd[k * PITCH + e] = z[(size_t)ds * 64 + k];
        }
        __syncthreads();

        float acc[2][8];

        // ---- e1 = relu(delta @ We1 + be1) ----
#pragma unroll
        for (int i = 0; i < 2; ++i)
#pragma unroll
            for (int j = 0; j < 8; ++j) acc[i][j] = 0.0f;
        gemm_chunk(sDelta, sWe1, 3, c0, e0, acc);
#pragma unroll
        for (int i = 0; i < 2; ++i) {
            float b = sbe1[c0 + i];
#pragma unroll
            for (int j = 0; j < 8; ++j)
                sBuf[(c0 + i) * PITCH + e0 + j] = fmaxf(acc[i][j] + b, 0.0f);
        }
        __syncthreads();

        // ---- e = relu(e1 @ We2 + be2) ----
#pragma unroll
        for (int i = 0; i < 2; ++i)
#pragma unroll
            for (int j = 0; j < 8; ++j) acc[i][j] = 0.0f;
        gemm_chunk(sBuf, sWe2, 64, c0, e0, acc);
#pragma unroll
        for (int i = 0; i < 2; ++i) {
            float b = sbe2[c0 + i];
#pragma unroll
            for (int j = 0; j < 8; ++j)
                sEf[(c0 + i) * PITCH + e0 + j] = fmaxf(acc[i][j] + b, 0.0f);
        }
        __syncthreads();

        // ---- m1 = relu([zs, zd, e] @ Wm1 + bm1) ----
#pragma unroll
        for (int i = 0; i < 2; ++i)
#pragma unroll
            for (int j = 0; j < 8; ++j) acc[i][j] = 0.0f;
        gemm_chunk(sZs, sWm1, 64, c0, e0, acc);
        gemm_chunk(sZd, sWm1 + 64 * 64, 64, c0, e0, acc);
        gemm_chunk(sEf, sWm1 + 128 * 64, 64, c0, e0, acc);
#pragma unroll
        for (int i = 0; i < 2; ++i) {
            float b = sbm1[c0 + i];
#pragma unroll
            for (int j = 0; j < 8; ++j)
                sBuf[(c0 + i) * PITCH + e0 + j] = fmaxf(acc[i][j] + b, 0.0f);
        }
        __syncthreads();

        // ---- m = m1 @ Wm2 + bm2 ----
#pragma unroll
        for (int i = 0; i < 2; ++i)
#pragma unroll
            for (int j = 0; j < 8; ++j) acc[i][j] = 0.0f;
        gemm_chunk(sBuf, sWm2, 64, c0, e0, acc);
#pragma unroll
        for (int i = 0; i < 2; ++i) {
            float b = sbm2[c0 + i];
#pragma unroll
            for (int j = 0; j < 8; ++j)
                sZs[(e0 + j) * PITCH + c0 + i] = acc[i][j] + b;
        }
        __syncthreads();

        // ---- scatter-add into sums[dst] ----
        for (int i = tid; i < TE * 64; i += TPB) {
            int e = i >> 6, c = i & 63;
            int d = sDst[e];
            if (d >= 0)
                atomicAdd(&sums[(size_t)d * 64 + c], sZs[e * PITCH + c]);
        }
        if (tid < TE && sDst[tid] >= 0) atomicAdd(&g_cnt[sDst[tid]], 1.0f);
        __syncthreads();
    }
}

// node_kernel smem: Wu1 8192 | bu1 64 | Zt 4160 | Mt 4160 = 16576 floats
__global__ __launch_bounds__(TPB) void node_kernel(
    const float* __restrict__ z, const float* __restrict__ sums,
    const float* __restrict__ Wu1, const float* __restrict__ bu1,
    float* __restrict__ out, int N, int ntiles) {
    extern __shared__ float sm[];
    float* sWu1 = sm;
    float* sbu1 = sm + 8192;
    float* sZ = sm + 8256;
    float* sM = sm + 12416;

    const int tid = threadIdx.x;
    for (int i = tid; i < 8192; i += TPB) sWu1[i] = Wu1[i];
    if (tid < 64) sbu1[tid] = bu1[tid];
    __syncthreads();

    const int cg = tid >> 3, eg = tid & 7;
    const int c0 = cg * 2, e0 = eg * 8;

    for (int tile = blockIdx.x; tile < ntiles; tile += gridDim.x) {
        const int base = tile * TE;
        for (int i = tid; i < TE * 64; i += TPB) {
            int nl = i >> 6, k = i & 63;
            int gn = base + nl;
            float zv = 0.0f, mv = 0.0f;
            if (gn < N) {
                zv = z[(size_t)gn * 64 + k];
                float c = fmaxf(g_cnt[gn], 1.0f);
                mv = sums[(size_t)gn * 64 + k] / c;
            }
            sZ[k * PITCH + nl] = zv;
            sM[k * PITCH + nl] = mv;
        }
        __syncthreads();

        float acc[2][8];
#pragma unroll
        for (int i = 0; i < 2; ++i)
#pragma unroll
            for (int j = 0; j < 8; ++j) acc[i][j] = 0.0f;
        gemm_chunk(sZ, sWu1, 64, c0, e0, acc);
        gemm_chunk(sM, sWu1 + 64 * 64, 64, c0, e0, acc);
        __syncthreads();

#pragma unroll
        for (int i = 0; i < 2; ++i) {
            float b = sbu1[c0 + i];
#pragma unroll
            for (int j = 0; j < 8; ++j)
                sZ[(e0 + j) * PITCH + c0 + i] = fmaxf(acc[i][j] + b, 0.0f);
        }
        __syncthreads();

        for (int i = tid; i < TE * 64; i += TPB) {
            int nl = i >> 6, c = i & 63;
            if (base + nl < N)
                out[(size_t)(base + nl) * 64 + c] = sZ[nl * PITCH + c];
        }
        __syncthreads();
    }
}

extern "C" void kernel_launch(void* const* d_in, const int* in_sizes, int n_in,
                              void* d_out, int out_size) {
    const float* z    = (const float*)d_in[0];
    const float* cent = (const float*)d_in[1];
    const void* ei    = d_in[2];
    const float* We1 = (const float*)d_in[3];
    const float* be1 = (const float*)d_in[4];
    const float* We2 = (const float*)d_in[5];
    const float* be2 = (const float*)d_in[6];
    const float* Wm1 = (const float*)d_in[7];
    const float* bm1 = (const float*)d_in[8];
    const float* Wm2 = (const float*)d_in[9];
    const float* bm2 = (const float*)d_in[10];
    const float* Wu1 = (const float*)d_in[11];
    const float* bu1 = (const float*)d_in[12];
    float* out = (float*)d_out;

    const int N = in_sizes[0] / 64;
    const int E = in_sizes[2] / 2;
    const int ntiles_e = (E + TE - 1) / TE;
    const int ntiles_n = (N + TE - 1) / TE;

    const size_t smem_edge = 37764 * sizeof(float) + 128 * sizeof(int);
    const size_t smem_node = 16576 * sizeof(float);

    cudaFuncSetAttribute(edge_kernel,
                         cudaFuncAttributeMaxDynamicSharedMemorySize,
                         (int)smem_edge);
    cudaFuncSetAttribute(node_kernel,
                         cudaFuncAttributeMaxDynamicSharedMemorySize,
                         (int)smem_node);

    detect_kernel<<<1, 32>>>((const unsigned long long*)ei);
    zero_kernel<<<(N * 64 + 255) / 256, 256>>>(out, N * 64, N);
    edge_kernel<<<148, TPB, smem_edge>>>(z, cent, ei,
                                         We1, be1, We2, be2,
                                         Wm1, bm1, Wm2, bm2,
                                         out, E, N, ntiles_e);
    node_kernel<<<444, TPB, smem_node>>>(z, out, Wu1, bu1, out, N, ntiles_n);
}

// round 3
// speedup vs baseline: 2.0147x; 2.0147x over previous
#include <cuda_runtime.h>

// SPConv fused GNN, R3: P/Q precompute + 4x8 register tiles + float4 LDS.

#define TPB 256
#define TE 128        // edges (or nodes) per tile
#define AP 132        // activation smem pitch (mult of 4 for float4 align)

__device__ float g_cnt[65536];
__device__ int g_idx64;
__device__ float g_P[3276800];   // z @ Wm1[0:64]    (51200 x 64 max)
__device__ float g_Q[3276800];   // z @ Wm1[64:128]

__global__ void detect_kernel(const unsigned long long* __restrict__ ei) {
    if (threadIdx.x == 0 && blockIdx.x == 0) {
        int is64 = 1;
        for (int i = 0; i < 64; ++i)
            if ((ei[i] >> 32) != 0ull) { is64 = 0; break; }
        g_idx64 = is64;
    }
}

__global__ void zero_kernel(float* __restrict__ sums, int total, int n) {
    int i = blockIdx.x * blockDim.x + threadIdx.x;
    if (i < total) sums[i] = 0.0f;
    if (i < n) g_cnt[i] = 0.0f;
}

// acc[4][8] += H[k][e0..e0+7] * W[k][c0..c0+3]; H:[K][hp] k-major, W:[K][64]
__device__ __forceinline__ void gemm4x8(const float* __restrict__ H, int hp,
                                        const float* __restrict__ W, int K,
                                        int c0, int e0, float acc[4][8]) {
#pragma unroll 4
    for (int k = 0; k < K; ++k) {
        float4 w = *reinterpret_cast<const float4*>(W + k * 64 + c0);
        float4 ha = *reinterpret_cast<const float4*>(H + k * hp + e0);
        float4 hb = *reinterpret_cast<const float4*>(H + k * hp + e0 + 4);
        float wv[4] = {w.x, w.y, w.z, w.w};
        float hv[8] = {ha.x, ha.y, ha.z, ha.w, hb.x, hb.y, hb.z, hb.w};
#pragma unroll
        for (int i = 0; i < 4; ++i)
#pragma unroll
            for (int j = 0; j < 8; ++j)
                acc[i][j] = fmaf(wv[i], hv[j], acc[i][j]);
    }
}

__device__ __forceinline__ void zero_acc(float acc[4][8]) {
#pragma unroll
    for (int i = 0; i < 4; ++i)
#pragma unroll
        for (int j = 0; j < 8; ++j) acc[i][j] = 0.0f;
}

// store relu(acc + bias) -> D[(c0+i)][e0..e0+7], pitch AP
__device__ __forceinline__ void store_relu(float* __restrict__ D,
                                           const float acc[4][8],
                                           const float* __restrict__ bias,
                                           int c0, int e0) {
#pragma unroll
    for (int i = 0; i < 4; ++i) {
        float b = bias[c0 + i];
        float4 v0, v1;
        v0.x = fmaxf(acc[i][0] + b, 0.0f); v0.y = fmaxf(acc[i][1] + b, 0.0f);
        v0.z = fmaxf(acc[i][2] + b, 0.0f); v0.w = fmaxf(acc[i][3] + b, 0.0f);
        v1.x = fmaxf(acc[i][4] + b, 0.0f); v1.y = fmaxf(acc[i][5] + b, 0.0f);
        v1.z = fmaxf(acc[i][6] + b, 0.0f); v1.w = fmaxf(acc[i][7] + b, 0.0f);
        *reinterpret_cast<float4*>(D + (c0 + i) * AP + e0) = v0;
        *reinterpret_cast<float4*>(D + (c0 + i) * AP + e0 + 4) = v1;
    }
}

// ---- pq_kernel: P = z @ Wm1[0:64], Q = z @ Wm1[64:128] ----
// smem: sW 8192 | sZ 64*AP = 8448  -> 16640 floats
__global__ __launch_bounds__(TPB) void pq_kernel(
    const float* __restrict__ z, const float* __restrict__ Wm1,
    int N, int ntiles) {
    extern __shared__ float sm[];
    float* sW = sm;
    float* sZ = sm + 8192;
    const int tid = threadIdx.x;
    for (int i = tid; i < 8192; i += TPB) sW[i] = Wm1[i];
    __syncthreads();

    const int cg = tid >> 4, eg = tid & 15;
    const int c0 = cg * 4, e0 = eg * 8;

    for (int tile = blockIdx.x; tile < ntiles; tile += gridDim.x) {
        const int base = tile * TE;
        for (int i = tid; i < 64 * TE; i += TPB) {
            int nl = i >> 6, k = i & 63;
            int gn = base + nl;
            sZ[k * AP + nl] = (gn < N) ? z[(size_t)gn * 64 + k] : 0.0f;
        }
        __syncthreads();

        float acc[4][8];
        zero_acc(acc);
        gemm4x8(sZ, AP, sW, 64, c0, e0, acc);
#pragma unroll
        for (int j = 0; j < 8; ++j) {
            int gn = base + e0 + j;
            if (gn < N) {
                float4 v = make_float4(acc[0][j], acc[1][j], acc[2][j], acc[3][j]);
                *reinterpret_cast<float4*>(&g_P[(size_t)gn * 64 + c0]) = v;
            }
        }
        zero_acc(acc);
        gemm4x8(sZ, AP, sW + 64 * 64, 64, c0, e0, acc);
#pragma unroll
        for (int j = 0; j < 8; ++j) {
            int gn = base + e0 + j;
            if (gn < N) {
                float4 v = make_float4(acc[0][j], acc[1][j], acc[2][j], acc[3][j]);
                *reinterpret_cast<float4*>(&g_Q[(size_t)gn * 64 + c0]) = v;
            }
        }
        __syncthreads();
    }
}

// ---- edge_kernel ----
// smem floats:
//      0 : sWe2  4096
//   4096 : sWm1c 4096  (Wm1 rows 128..191)
//   8192 : sWm2  4096
//  12288 : sWe1   192
//  12480 : be1 | 12544 : be2 | 12608 : bm1 | 12672 : bm2
//  12736 : sDelta 3*AP = 396
//  13132 : sA 64*AP = 8448
//  21580 : sB 8448
//  30028 : sPQ 8448
//  38476 : src/dst (2*TE ints)
__global__ __launch_bounds__(TPB) void edge_kernel(
    const float* __restrict__ cent, const void* __restrict__ ei_raw,
    const float* __restrict__ We1, const float* __restrict__ be1,
    const float* __restrict__ We2, const float* __restrict__ be2,
    const float* __restrict__ Wm1, const float* __restrict__ bm1,
    const float* __restrict__ Wm2, const float* __restrict__ bm2,
    float* __restrict__ sums, int E, int N, int ntiles) {
    extern __shared__ float sm[];
    float* sWe2 = sm;
    float* sWm1c = sm + 4096;
    float* sWm2 = sm + 8192;
    float* sWe1 = sm + 12288;
    float* sbe1 = sm + 12480;
    float* sbe2 = sm + 12544;
    float* sbm1 = sm + 12608;
    float* sbm2 = sm + 12672;
    float* sDelta = sm + 12736;
    float* sA = sm + 13132;
    float* sB = sm + 21580;
    float* sPQ = sm + 30028;
    int* sSrc = (int*)(sm + 38476);
    int* sDst = sSrc + TE;

    const int tid = threadIdx.x;
    const int idx64 = g_idx64;
    const long long* ei64 = (const long long*)ei_raw;
    const int* ei32 = (const int*)ei_raw;

    for (int i = tid; i < 4096; i += TPB) {
        sWe2[i] = We2[i];
        sWm1c[i] = Wm1[128 * 64 + i];
        sWm2[i] = Wm2[i];
    }
    if (tid < 192) sWe1[tid] = We1[tid];
    if (tid < 64) {
        sbe1[tid] = be1[tid]; sbe2[tid] = be2[tid];
        sbm1[tid] = bm1[tid]; sbm2[tid] = bm2[tid];
    }
    __syncthreads();

    const int cg = tid >> 4, eg = tid & 15;
    const int c0 = cg * 4, e0 = eg * 8;

    for (int tile = blockIdx.x; tile < ntiles; tile += gridDim.x) {
        const int base = tile * TE;

        if (tid < TE) {
            int e = base + tid;
            int s = 0, d = -1;
            if (e < E) {
                if (idx64) { s = (int)ei64[e]; d = (int)ei64[(size_t)E + e]; }
                else       { s = ei32[e];      d = ei32[E + e]; }
                if (s < 0 || s >= N) s = 0;
                if (d < 0 || d >= N) d = 0;
            }
            sSrc[tid] = s;
            sDst[tid] = d;
        }
        __syncthreads();

        // delta = centroids[dst] - centroids[src]
        for (int i = tid; i < 3 * TE; i += TPB) {
            int e = i & 127, comp = i >> 7;
            int s = sSrc[e], d = sDst[e];
            int dd = (d < 0) ? s : d;
            sDelta[comp * AP + e] =
                cent[(size_t)dd * 3 + comp] - cent[(size_t)s * 3 + comp];
        }
        // PQ = P[src] + Q[dst], k-major [64][AP]
        for (int i = tid; i < 64 * TE; i += TPB) {
            int e = i >> 6, k = i & 63;
            int s = sSrc[e], d = sDst[e];
            int dd = (d < 0) ? s : d;
            sPQ[k * AP + e] = g_P[(size_t)s * 64 + k] + g_Q[(size_t)dd * 64 + k];
        }
        __syncthreads();

        float acc[4][8];

        // L1: e1 = relu(delta @ We1 + be1) -> sA
        zero_acc(acc);
        gemm4x8(sDelta, AP, sWe1, 3, c0, e0, acc);
        store_relu(sA, acc, sbe1, c0, e0);
        __syncthreads();

        // L2: e = relu(e1 @ We2 + be2) -> sB
        zero_acc(acc);
        gemm4x8(sA, AP, sWe2, 64, c0, e0, acc);
        store_relu(sB, acc, sbe2, c0, e0);
        __syncthreads();

        // L3: m1 = relu(e @ Wm1c + P[s] + Q[d] + bm1) -> sA
#pragma unroll
        for (int i = 0; i < 4; ++i) {
            float4 a = *reinterpret_cast<const float4*>(sPQ + (c0 + i) * AP + e0);
            float4 b = *reinterpret_cast<const float4*>(sPQ + (c0 + i) * AP + e0 + 4);
            acc[i][0] = a.x; acc[i][1] = a.y; acc[i][2] = a.z; acc[i][3] = a.w;
            acc[i][4] = b.x; acc[i][5] = b.y; acc[i][6] = b.z; acc[i][7] = b.w;
        }
        gemm4x8(sB, AP, sWm1c, 64, c0, e0, acc);
        store_relu(sA, acc, sbm1, c0, e0);
        __syncthreads();

        // L4: m = m1 @ Wm2 + bm2 -> scatter-add to sums[dst]
        zero_acc(acc);
        gemm4x8(sA, AP, sWm2, 64, c0, e0, acc);
#pragma unroll
        for (int j = 0; j < 8; ++j) {
            int d = sDst[e0 + j];
            if (d >= 0) {
                float* p = &sums[(size_t)d * 64 + c0];
#pragma unroll
                for (int i = 0; i < 4; ++i)
                    atomicAdd(p + i, acc[i][j] + sbm2[c0 + i]);
            }
        }
        if (tid < TE && sDst[tid] >= 0) atomicAdd(&g_cnt[sDst[tid]], 1.0f);
        __syncthreads();
    }
}

// ---- out_kernel: out = relu([z, sums/cnt] @ Wu1 + bu1), in-place on sums ----
// smem: sW 8192 | sb 64 | sZM 128*AP = 16896  -> 25152 floats
__global__ __launch_bounds__(TPB) void out_kernel(
    const float* __restrict__ z, const float* __restrict__ sums,
    const float* __restrict__ Wu1, const float* __restrict__ bu1,
    float* __restrict__ out, int N, int ntiles) {
    extern __shared__ float sm[];
    float* sW = sm;
    float* sb = sm + 8192;
    float* sZM = sm + 8256;

    const int tid = threadIdx.x;
    for (int i = tid; i < 8192; i += TPB) sW[i] = Wu1[i];
    if (tid < 64) sb[tid] = bu1[tid];
    __syncthreads();

    const int cg = tid >> 4, eg = tid & 15;
    const int c0 = cg * 4, e0 = eg * 8;

    for (int tile = blockIdx.x; tile < ntiles; tile += gridDim.x) {
        const int base = tile * TE;
        for (int i = tid; i < 128 * TE; i += TPB) {
            int nl = i >> 7, k = i & 127;
            int gn = base + nl;
            float v = 0.0f;
            if (gn < N) {
                if (k < 64) {
                    v = z[(size_t)gn * 64 + k];
                } else {
                    float c = fmaxf(g_cnt[gn], 1.0f);
                    v = sums[(size_t)gn * 64 + (k - 64)] / c;
                }
            }
            sZM[k * AP + nl] = v;
        }
        __syncthreads();

        float acc[4][8];
        zero_acc(acc);
        gemm4x8(sZM, AP, sW, 128, c0, e0, acc);

#pragma unroll
        for (int j = 0; j < 8; ++j) {
            int gn = base + e0 + j;
            if (gn < N) {
                float4 v;
                v.x = fmaxf(acc[0][j] + sb[c0 + 0], 0.0f);
                v.y = fmaxf(acc[1][j] + sb[c0 + 1], 0.0f);
                v.z = fmaxf(acc[2][j] + sb[c0 + 2], 0.0f);
                v.w = fmaxf(acc[3][j] + sb[c0 + 3], 0.0f);
                *reinterpret_cast<float4*>(&out[(size_t)gn * 64 + c0]) = v;
            }
        }
        __syncthreads();
    }
}

extern "C" void kernel_launch(void* const* d_in, const int* in_sizes, int n_in,
                              void* d_out, int out_size) {
    const float* z    = (const float*)d_in[0];
    const float* cent = (const float*)d_in[1];
    const void* ei    = d_in[2];
    const float* We1 = (const float*)d_in[3];
    const float* be1 = (const float*)d_in[4];
    const float* We2 = (const float*)d_in[5];
    const float* be2 = (const float*)d_in[6];
    const float* Wm1 = (const float*)d_in[7];
    const float* bm1 = (const float*)d_in[8];
    const float* Wm2 = (const float*)d_in[9];
    const float* bm2 = (const float*)d_in[10];
    const float* Wu1 = (const float*)d_in[11];
    const float* bu1 = (const float*)d_in[12];
    float* out = (float*)d_out;

    const int N = in_sizes[0] / 64;
    const int E = in_sizes[2] / 2;
    const int ntiles_e = (E + TE - 1) / TE;
    const int ntiles_n = (N + TE - 1) / TE;

    const size_t smem_edge = 38476 * sizeof(float) + 2 * TE * sizeof(int);
    const size_t smem_pq   = 16640 * sizeof(float);
    const size_t smem_out  = 25152 * sizeof(float);

    cudaFuncSetAttribute(edge_kernel, cudaFuncAttributeMaxDynamicSharedMemorySize,
                         (int)smem_edge);
    cudaFuncSetAttribute(pq_kernel, cudaFuncAttributeMaxDynamicSharedMemorySize,
                         (int)smem_pq);
    cudaFuncSetAttribute(out_kernel, cudaFuncAttributeMaxDynamicSharedMemorySize,
                         (int)smem_out);

    detect_kernel<<<1, 32>>>((const unsigned long long*)ei);
    zero_kernel<<<(N * 64 + 255) / 256, 256>>>(out, N * 64, N);
    pq_kernel<<<ntiles_n, TPB, smem_pq>>>(z, Wm1, N, ntiles_n);
    edge_kernel<<<148, TPB, smem_edge>>>(cent, ei,
                                         We1, be1, We2, be2,
                                         Wm1, bm1, Wm2, bm2,
                                         out, E, N, ntiles_e);
    out_kernel<<<ntiles_n, TPB, smem_out>>>(z, out, Wu1, bu1, out, N, ntiles_n);
}

// round 4
// speedup vs baseline: 2.0179x; 1.0016x over previous
#include <cuda_runtime.h>

// SPConv fused GNN, R4: fma.rn.f32x2 packed math, TPB=512/TE=256, PQ direct-init.

#define TPB 512
#define TE 256        // edges (or nodes) per tile
#define AP 260        // activation smem pitch (floats, mult of 4)

typedef unsigned long long ull;

__device__ float g_cnt[65536];
__device__ int g_idx64;
__device__ float g_P[3276800];   // z @ Wm1[0:64]
__device__ float g_Q[3276800];   // z @ Wm1[64:128]

__device__ __forceinline__ void ffma2(ull& acc, ull a, ull b) {
    asm("fma.rn.f32x2 %0, %1, %2, %0;" : "+l"(acc) : "l"(a), "l"(b));
}
__device__ __forceinline__ ull dup2(float w) {
    ull r;
    asm("mov.b64 %0, {%1, %1};" : "=l"(r) : "r"(__float_as_uint(w)));
    return r;
}
__device__ __forceinline__ ull pack2(float lo, float hi) {
    ull r;
    asm("mov.b64 %0, {%1, %2};" : "=l"(r)
        : "r"(__float_as_uint(lo)), "r"(__float_as_uint(hi)));
    return r;
}
__device__ __forceinline__ void unpack2(ull v, float& lo, float& hi) {
    unsigned a, b;
    asm("mov.b64 {%0, %1}, %2;" : "=r"(a), "=r"(b) : "l"(v));
    lo = __uint_as_float(a);
    hi = __uint_as_float(b);
}

__global__ void detect_kernel(const unsigned long long* __restrict__ ei) {
    if (threadIdx.x == 0 && blockIdx.x == 0) {
        int is64 = 1;
        for (int i = 0; i < 64; ++i)
            if ((ei[i] >> 32) != 0ull) { is64 = 0; break; }
        g_idx64 = is64;
    }
}

__global__ void zero_kernel(float* __restrict__ sums, int total, int n) {
    int i = blockIdx.x * blockDim.x + threadIdx.x;
    if (i < total) sums[i] = 0.0f;
    if (i < n) g_cnt[i] = 0.0f;
}

// Packed GEMM: acc[4ch][4 edge-pairs] += H[k][e0..e0+7] * W[k][c0..c0+3]
__device__ __forceinline__ void gemmp(const float* __restrict__ H, int hp,
                                      const float* __restrict__ W, int K,
                                      int c0, int e0, ull acc[4][4]) {
#pragma unroll 4
    for (int k = 0; k < K; ++k) {
        float4 w = *reinterpret_cast<const float4*>(W + k * 64 + c0);
        ull w2[4] = {dup2(w.x), dup2(w.y), dup2(w.z), dup2(w.w)};
        const float* hr = H + k * hp + e0;
        ulonglong2 hA = *reinterpret_cast<const ulonglong2*>(hr);
        ulonglong2 hB = *reinterpret_cast<const ulonglong2*>(hr + 4);
        ull h2[4] = {hA.x, hA.y, hB.x, hB.y};
#pragma unroll
        for (int i = 0; i < 4; ++i)
#pragma unroll
            for (int jp = 0; jp < 4; ++jp)
                ffma2(acc[i][jp], h2[jp], w2[i]);
    }
}

__device__ __forceinline__ void zero_acc(ull acc[4][4]) {
#pragma unroll
    for (int i = 0; i < 4; ++i)
#pragma unroll
        for (int jp = 0; jp < 4; ++jp) acc[i][jp] = 0ull;
}

// store relu(acc + bias) -> D[(c0+i)][e0..e0+7], pitch AP
__device__ __forceinline__ void store_relu(float* __restrict__ D,
                                           ull acc[4][4],
                                           const float* __restrict__ bias,
                                           int c0, int e0) {
#pragma unroll
    for (int i = 0; i < 4; ++i) {
        float b = bias[c0 + i];
        float v[8];
#pragma unroll
        for (int jp = 0; jp < 4; ++jp) unpack2(acc[i][jp], v[2 * jp], v[2 * jp + 1]);
        float4 v0, v1;
        v0.x = fmaxf(v[0] + b, 0.0f); v0.y = fmaxf(v[1] + b, 0.0f);
        v0.z = fmaxf(v[2] + b, 0.0f); v0.w = fmaxf(v[3] + b, 0.0f);
        v1.x = fmaxf(v[4] + b, 0.0f); v1.y = fmaxf(v[5] + b, 0.0f);
        v1.z = fmaxf(v[6] + b, 0.0f); v1.w = fmaxf(v[7] + b, 0.0f);
        *reinterpret_cast<float4*>(D + (c0 + i) * AP + e0) = v0;
        *reinterpret_cast<float4*>(D + (c0 + i) * AP + e0 + 4) = v1;
    }
}

// ---- pq_kernel: P = z @ Wm1[0:64], Q = z @ Wm1[64:128] ----
// smem: sW 8192 | sZ 64*AP=16640  -> 24832 floats
__global__ __launch_bounds__(TPB) void pq_kernel(
    const float* __restrict__ z, const float* __restrict__ Wm1,
    int N, int ntiles) {
    extern __shared__ float sm[];
    float* sW = sm;
    float* sZ = sm + 8192;
    const int tid = threadIdx.x;
    for (int i = tid; i < 8192; i += TPB) sW[i] = Wm1[i];
    __syncthreads();

    const int c0 = (tid >> 5) * 4, e0 = (tid & 31) * 8;

    for (int tile = blockIdx.x; tile < ntiles; tile += gridDim.x) {
        const int base = tile * TE;
        for (int i = tid; i < 64 * TE; i += TPB) {
            int nl = i >> 6, k = i & 63;
            int gn = base + nl;
            sZ[k * AP + nl] = (gn < N) ? z[(size_t)gn * 64 + k] : 0.0f;
        }
        __syncthreads();

        ull acc[4][4];
#pragma unroll
        for (int pass = 0; pass < 2; ++pass) {
            zero_acc(acc);
            gemmp(sZ, AP, sW + pass * 64 * 64, 64, c0, e0, acc);
            float v[4][8];
#pragma unroll
            for (int i = 0; i < 4; ++i)
#pragma unroll
                for (int jp = 0; jp < 4; ++jp)
                    unpack2(acc[i][jp], v[i][2 * jp], v[i][2 * jp + 1]);
            float* dst = pass == 0 ? g_P : g_Q;
#pragma unroll
            for (int j = 0; j < 8; ++j) {
                int gn = base + e0 + j;
                if (gn < N) {
                    float4 o = make_float4(v[0][j], v[1][j], v[2][j], v[3][j]);
                    *reinterpret_cast<float4*>(&dst[(size_t)gn * 64 + c0]) = o;
                }
            }
        }
        __syncthreads();
    }
}

// ---- edge_kernel ----
// smem floats:
//      0 : sWe2  4096
//   4096 : sWm1c 4096 (Wm1 rows 128..191)
//   8192 : sWm2  4096
//  12288 : sWe1   192
//  12480 : be1 | 12544 : be2 | 12608 : bm1 | 12672 : bm2
//  12736 : sDelta 3*AP = 780
//  13516 : sA 64*AP = 16640
//  30156 : sB 16640
//  46796 : src/dst (2*TE ints)
__global__ __launch_bounds__(TPB) void edge_kernel(
    const float* __restrict__ cent, const void* __restrict__ ei_raw,
    const float* __restrict__ We1, const float* __restrict__ be1,
    const float* __restrict__ We2, const float* __restrict__ be2,
    const float* __restrict__ Wm1, const float* __restrict__ bm1,
    const float* __restrict__ Wm2, const float* __restrict__ bm2,
    float* __restrict__ sums, int E, int N, int ntiles) {
    extern __shared__ float sm[];
    float* sWe2 = sm;
    float* sWm1c = sm + 4096;
    float* sWm2 = sm + 8192;
    float* sWe1 = sm + 12288;
    float* sbe1 = sm + 12480;
    float* sbe2 = sm + 12544;
    float* sbm1 = sm + 12608;
    float* sbm2 = sm + 12672;
    float* sDelta = sm + 12736;
    float* sA = sm + 13516;
    float* sB = sm + 30156;
    int* sSrc = (int*)(sm + 46796);
    int* sDst = sSrc + TE;

    const int tid = threadIdx.x;
    const int idx64 = g_idx64;
    const long long* ei64 = (const long long*)ei_raw;
    const int* ei32 = (const int*)ei_raw;

    for (int i = tid; i < 4096; i += TPB) {
        sWe2[i] = We2[i];
        sWm1c[i] = Wm1[128 * 64 + i];
        sWm2[i] = Wm2[i];
    }
    if (tid < 192) sWe1[tid] = We1[tid];
    if (tid < 64) {
        sbe1[tid] = be1[tid]; sbe2[tid] = be2[tid];
        sbm1[tid] = bm1[tid]; sbm2[tid] = bm2[tid];
    }
    __syncthreads();

    const int c0 = (tid >> 5) * 4, e0 = (tid & 31) * 8;

    for (int tile = blockIdx.x; tile < ntiles; tile += gridDim.x) {
        const int base = tile * TE;

        if (tid < TE) {
            int e = base + tid;
            int s = 0, d = -1;
            if (e < E) {
                if (idx64) { s = (int)ei64[e]; d = (int)ei64[(size_t)E + e]; }
                else       { s = ei32[e];      d = ei32[E + e]; }
                if (s < 0 || s >= N) s = 0;
                if (d < 0 || d >= N) d = 0;
            }
            sSrc[tid] = s;
            sDst[tid] = d;
        }
        __syncthreads();

        // delta = centroids[dst] - centroids[src]
        for (int i = tid; i < 3 * TE; i += TPB) {
            int e = i & (TE - 1), comp = i >> 8;
            int s = sSrc[e], d = sDst[e];
            int dd = (d < 0) ? s : d;
            sDelta[comp * AP + e] =
                cent[(size_t)dd * 3 + comp] - cent[(size_t)s * 3 + comp];
        }
        __syncthreads();

        ull acc[4][4];

        // L1: e1 = relu(delta @ We1 + be1) -> sA
        zero_acc(acc);
        gemmp(sDelta, AP, sWe1, 3, c0, e0, acc);
        store_relu(sA, acc, sbe1, c0, e0);
        __syncthreads();

        // L2: e = relu(e1 @ We2 + be2) -> sB
        zero_acc(acc);
        gemmp(sA, AP, sWe2, 64, c0, e0, acc);
        store_relu(sB, acc, sbe2, c0, e0);
        __syncthreads();

        // L3: m1 = relu(e @ Wm1c + P[src] + Q[dst] + bm1) -> sA
        {
            float vv[4][8];
#pragma unroll
            for (int j = 0; j < 8; ++j) {
                int e = e0 + j;
                int s = sSrc[e], d = sDst[e];
                int dd = (d < 0) ? s : d;
                float4 p = *reinterpret_cast<const float4*>(&g_P[(size_t)s * 64 + c0]);
                float4 q = *reinterpret_cast<const float4*>(&g_Q[(size_t)dd * 64 + c0]);
                vv[0][j] = p.x + q.x; vv[1][j] = p.y + q.y;
                vv[2][j] = p.z + q.z; vv[3][j] = p.w + q.w;
            }
#pragma unroll
            for (int i = 0; i < 4; ++i)
#pragma unroll
                for (int jp = 0; jp < 4; ++jp)
                    acc[i][jp] = pack2(vv[i][2 * jp], vv[i][2 * jp + 1]);
        }
        gemmp(sB, AP, sWm1c, 64, c0, e0, acc);
        store_relu(sA, acc, sbm1, c0, e0);
        __syncthreads();

        // L4: m = m1 @ Wm2 + bm2 -> scatter-add to sums[dst]
        zero_acc(acc);
        gemmp(sA, AP, sWm2, 64, c0, e0, acc);
        {
            float v[4][8];
#pragma unroll
            for (int i = 0; i < 4; ++i)
#pragma unroll
                for (int jp = 0; jp < 4; ++jp)
                    unpack2(acc[i][jp], v[i][2 * jp], v[i][2 * jp + 1]);
#pragma unroll
            for (int j = 0; j < 8; ++j) {
                int d = sDst[e0 + j];
                if (d >= 0) {
                    float* p = &sums[(size_t)d * 64 + c0];
#pragma unroll
                    for (int i = 0; i < 4; ++i)
                        atomicAdd(p + i, v[i][j] + sbm2[c0 + i]);
                }
            }
        }
        if (tid < TE && sDst[tid] >= 0) atomicAdd(&g_cnt[sDst[tid]], 1.0f);
        __syncthreads();
    }
}

// ---- out_kernel: out = relu([z, sums/cnt] @ Wu1 + bu1) (in-place on sums) ----
// smem: sW 8192 | sb 64 | sZM 128*AP = 33280 -> 41536 floats
__global__ __launch_bounds__(TPB) void out_kernel(
    const float* __restrict__ z, const float* __restrict__ sums,
    const float* __restrict__ Wu1, const float* __restrict__ bu1,
    float* __restrict__ out, int N, int ntiles) {
    extern __shared__ float sm[];
    float* sW = sm;
    float* sb = sm + 8192;
    float* sZM = sm + 8256;

    const int tid = threadIdx.x;
    for (int i = tid; i < 8192; i += TPB) sW[i] = Wu1[i];
    if (tid < 64) sb[tid] = bu1[tid];
    __syncthreads();

    const int c0 = (tid >> 5) * 4, e0 = (tid & 31) * 8;

    for (int tile = blockIdx.x; tile < ntiles; tile += gridDim.x) {
        const int base = tile * TE;
        for (int i = tid; i < 128 * TE; i += TPB) {
            int nl = i >> 7, k = i & 127;
            int gn = base + nl;
            float v = 0.0f;
            if (gn < N) {
                if (k < 64) {
                    v = z[(size_t)gn * 64 + k];
                } else {
                    float c = fmaxf(g_cnt[gn], 1.0f);
                    v = sums[(size_t)gn * 64 + (k - 64)] / c;
                }
            }
            sZM[k * AP + nl] = v;
        }
        __syncthreads();

        ull acc[4][4];
        zero_acc(acc);
        gemmp(sZM, AP, sW, 128, c0, e0, acc);

        float v[4][8];
#pragma unroll
        for (int i = 0; i < 4; ++i)
#pragma unroll
            for (int jp = 0; jp < 4; ++jp)
                unpack2(acc[i][jp], v[i][2 * jp], v[i][2 * jp + 1]);
#pragma unroll
        for (int j = 0; j < 8; ++j) {
            int gn = base + e0 + j;
            if (gn < N) {
                float4 o;
                o.x = fmaxf(v[0][j] + sb[c0 + 0], 0.0f);
                o.y = fmaxf(v[1][j] + sb[c0 + 1], 0.0f);
                o.z = fmaxf(v[2][j] + sb[c0 + 2], 0.0f);
                o.w = fmaxf(v[3][j] + sb[c0 + 3], 0.0f);
                *reinterpret_cast<float4*>(&out[(size_t)gn * 64 + c0]) = o;
            }
        }
        __syncthreads();
    }
}

extern "C" void kernel_launch(void* const* d_in, const int* in_sizes, int n_in,
                              void* d_out, int out_size) {
    const float* z    = (const float*)d_in[0];
    const float* cent = (const float*)d_in[1];
    const void* ei    = d_in[2];
    const float* We1 = (const float*)d_in[3];
    const float* be1 = (const float*)d_in[4];
    const float* We2 = (const float*)d_in[5];
    const float* be2 = (const float*)d_in[6];
    const float* Wm1 = (const float*)d_in[7];
    const float* bm1 = (const float*)d_in[8];
    const float* Wm2 = (const float*)d_in[9];
    const float* bm2 = (const float*)d_in[10];
    const float* Wu1 = (const float*)d_in[11];
    const float* bu1 = (const float*)d_in[12];
    float* out = (float*)d_out;

    const int N = in_sizes[0] / 64;
    const int E = in_sizes[2] / 2;
    const int ntiles_e = (E + TE - 1) / TE;
    const int ntiles_n = (N + TE - 1) / TE;

    const size_t smem_edge = 46796 * sizeof(float) + 2 * TE * sizeof(int);
    const size_t smem_pq   = 24832 * sizeof(float);
    const size_t smem_out  = 41536 * sizeof(float);

    cudaFuncSetAttribute(edge_kernel, cudaFuncAttributeMaxDynamicSharedMemorySize,
                         (int)smem_edge);
    cudaFuncSetAttribute(pq_kernel, cudaFuncAttributeMaxDynamicSharedMemorySize,
                         (int)smem_pq);
    cudaFuncSetAttribute(out_kernel, cudaFuncAttributeMaxDynamicSharedMemorySize,
                         (int)smem_out);

    detect_kernel<<<1, 32>>>((const unsigned long long*)ei);
    zero_kernel<<<(N * 64 + 255) / 256, 256>>>(out, N * 64, N);
    pq_kernel<<<ntiles_n, TPB, smem_pq>>>(z, Wm1, N, ntiles_n);
    edge_kernel<<<148, TPB, smem_edge>>>(cent, ei,
                                         We1, be1, We2, be2,
                                         Wm1, bm1, Wm2, bm2,
                                         out, E, N, ntiles_e);
    out_kernel<<<ntiles_n, TPB, smem_out>>>(z, out, Wu1, bu1, out, N, ntiles_n);
}

// round 5
// speedup vs baseline: 2.9401x; 1.4570x over previous
#include <cuda_runtime.h>

// SPConv fused GNN, R5: conflict-free 8ch x 4edge tiles, channel-pair FFMA2,
// group-scoped named barriers.

#define TPB 512
#define TE 256        // edges (or nodes) per tile
#define AP 260        // activation smem pitch (floats, mult of 4)

typedef unsigned long long ull;

__device__ float g_cnt[65536];
__device__ int g_idx64;
__device__ float g_P[3276800];   // z @ Wm1[0:64]
__device__ float g_Q[3276800];   // z @ Wm1[64:128]

__device__ __forceinline__ void ffma2(ull& acc, ull a, ull b) {
    asm("fma.rn.f32x2 %0, %1, %2, %0;" : "+l"(acc) : "l"(a), "l"(b));
}
__device__ __forceinline__ ull dup2(float w) {
    ull r;
    asm("mov.b64 %0, {%1, %1};" : "=l"(r) : "r"(__float_as_uint(w)));
    return r;
}
__device__ __forceinline__ ull pack2(float lo, float hi) {
    ull r;
    asm("mov.b64 %0, {%1, %2};" : "=l"(r)
        : "r"(__float_as_uint(lo)), "r"(__float_as_uint(hi)));
    return r;
}
__device__ __forceinline__ void unpack2(ull v, float& lo, float& hi) {
    unsigned a, b;
    asm("mov.b64 {%0, %1}, %2;" : "=r"(a), "=r"(b) : "l"(v));
    lo = __uint_as_float(a);
    hi = __uint_as_float(b);
}
#define GROUP_BAR(g) asm volatile("bar.sync %0, 256;" :: "r"((g) + 1) : "memory")

__global__ void detect_kernel(const unsigned long long* __restrict__ ei) {
    if (threadIdx.x == 0 && blockIdx.x == 0) {
        int is64 = 1;
        for (int i = 0; i < 64; ++i)
            if ((ei[i] >> 32) != 0ull) { is64 = 0; break; }
        g_idx64 = is64;
    }
}

__global__ void zero_kernel(float* __restrict__ sums, int total, int n) {
    int i = blockIdx.x * blockDim.x + threadIdx.x;
    if (i < total) sums[i] = 0.0f;
    if (i < n) g_cnt[i] = 0.0f;
}

// acc[4 ch-pairs][4 edges]: channels cb..cb+7 (paired), edges eb..eb+3.
// W broadcast per warp (cb uniform in warp), H dense float4 per lane.
__device__ __forceinline__ void gemmp(const float* __restrict__ H, int hp,
                                      const float* __restrict__ W, int K,
                                      int cb, int eb, ull acc[4][4]) {
#pragma unroll 4
    for (int k = 0; k < K; ++k) {
        ulonglong2 wA = *reinterpret_cast<const ulonglong2*>(W + k * 64 + cb);
        ulonglong2 wB = *reinterpret_cast<const ulonglong2*>(W + k * 64 + cb + 4);
        ull w2[4] = {wA.x, wA.y, wB.x, wB.y};
        float4 h = *reinterpret_cast<const float4*>(H + k * hp + eb);
        ull h2[4] = {dup2(h.x), dup2(h.y), dup2(h.z), dup2(h.w)};
#pragma unroll
        for (int cp = 0; cp < 4; ++cp)
#pragma unroll
            for (int e = 0; e < 4; ++e)
                ffma2(acc[cp][e], w2[cp], h2[e]);
    }
}

__device__ __forceinline__ void zero_acc(ull acc[4][4]) {
#pragma unroll
    for (int cp = 0; cp < 4; ++cp)
#pragma unroll
        for (int e = 0; e < 4; ++e) acc[cp][e] = 0ull;
}

// relu(acc + bias) -> D[ch][eb..eb+3] as float4 rows (dense STS.128)
__device__ __forceinline__ void store_relu(float* __restrict__ D,
                                           ull acc[4][4],
                                           const float* __restrict__ bias,
                                           int cb, int eb) {
#pragma unroll
    for (int cp = 0; cp < 4; ++cp) {
        float lo[4], hi[4];
#pragma unroll
        for (int e = 0; e < 4; ++e) unpack2(acc[cp][e], lo[e], hi[e]);
        float b0 = bias[cb + 2 * cp], b1 = bias[cb + 2 * cp + 1];
        float4 v0, v1;
        v0.x = fmaxf(lo[0] + b0, 0.0f); v0.y = fmaxf(lo[1] + b0, 0.0f);
        v0.z = fmaxf(lo[2] + b0, 0.0f); v0.w = fmaxf(lo[3] + b0, 0.0f);
        v1.x = fmaxf(hi[0] + b1, 0.0f); v1.y = fmaxf(hi[1] + b1, 0.0f);
        v1.z = fmaxf(hi[2] + b1, 0.0f); v1.w = fmaxf(hi[3] + b1, 0.0f);
        *reinterpret_cast<float4*>(D + (cb + 2 * cp) * AP + eb) = v0;
        *reinterpret_cast<float4*>(D + (cb + 2 * cp + 1) * AP + eb) = v1;
    }
}

// ---- pq_kernel: P = z @ Wm1[0:64], Q = z @ Wm1[64:128] ----
// smem: sW 8192 | sZ 64*AP=16640  -> 24832 floats
__global__ __launch_bounds__(TPB) void pq_kernel(
    const float* __restrict__ z, const float* __restrict__ Wm1,
    int N, int ntiles) {
    extern __shared__ float sm[];
    float* sW = sm;
    float* sZ = sm + 8192;
    const int tid = threadIdx.x;
    for (int i = tid; i < 8192; i += TPB) sW[i] = Wm1[i];
    __syncthreads();

    const int wid = tid >> 5, lane = tid & 31;
    const int grp = wid >> 3;
    const int cb = (wid & 7) * 8;
    const int eb = grp * 128 + lane * 4;

    for (int tile = blockIdx.x; tile < ntiles; tile += gridDim.x) {
        const int base = tile * TE;
        for (int i = tid; i < 64 * TE; i += TPB) {
            int nl = i >> 6, k = i & 63;
            int gn = base + nl;
            sZ[k * AP + nl] = (gn < N) ? z[(size_t)gn * 64 + k] : 0.0f;
        }
        __syncthreads();

        ull acc[4][4];
#pragma unroll
        for (int pass = 0; pass < 2; ++pass) {
            zero_acc(acc);
            gemmp(sZ, AP, sW + pass * 64 * 64, 64, cb, eb, acc);
            float* dst = pass == 0 ? g_P : g_Q;
#pragma unroll
            for (int e = 0; e < 4; ++e) {
                int gn = base + eb + e;
                if (gn < N) {
                    float v[8];
#pragma unroll
                    for (int cp = 0; cp < 4; ++cp)
                        unpack2(acc[cp][e], v[2 * cp], v[2 * cp + 1]);
                    *reinterpret_cast<float4*>(&dst[(size_t)gn * 64 + cb]) =
                        make_float4(v[0], v[1], v[2], v[3]);
                    *reinterpret_cast<float4*>(&dst[(size_t)gn * 64 + cb + 4]) =
                        make_float4(v[4], v[5], v[6], v[7]);
                }
            }
        }
        __syncthreads();
    }
}

// ---- edge_kernel ----
// smem floats:
//      0 : sWe2  4096
//   4096 : sWm1c 4096 (Wm1 rows 128..191)
//   8192 : sWm2  4096
//  12288 : sWe1   192
//  12480 : be1 | 12544 : be2 | 12608 : bm1 | 12672 : bm2
//  12736 : sDelta 3*AP = 780
//  13516 : sA 64*AP = 16640
//  30156 : sB 16640
//  46796 : src/dst (2*TE ints)
__global__ __launch_bounds__(TPB) void edge_kernel(
    const float* __restrict__ cent, const void* __restrict__ ei_raw,
    const float* __restrict__ We1, const float* __restrict__ be1,
    const float* __restrict__ We2, const float* __restrict__ be2,
    const float* __restrict__ Wm1, const float* __restrict__ bm1,
    const float* __restrict__ Wm2, const float* __restrict__ bm2,
    float* __restrict__ sums, int E, int N, int ntiles) {
    extern __shared__ float sm[];
    float* sWe2 = sm;
    float* sWm1c = sm + 4096;
    float* sWm2 = sm + 8192;
    float* sWe1 = sm + 12288;
    float* sbe1 = sm + 12480;
    float* sbe2 = sm + 12544;
    float* sbm1 = sm + 12608;
    float* sbm2 = sm + 12672;
    float* sDelta = sm + 12736;
    float* sA = sm + 13516;
    float* sB = sm + 30156;
    int* sSrc = (int*)(sm + 46796);
    int* sDst = sSrc + TE;

    const int tid = threadIdx.x;
    const int idx64 = g_idx64;
    const long long* ei64 = (const long long*)ei_raw;
    const int* ei32 = (const int*)ei_raw;

    for (int i = tid; i < 4096; i += TPB) {
        sWe2[i] = We2[i];
        sWm1c[i] = Wm1[128 * 64 + i];
        sWm2[i] = Wm2[i];
    }
    if (tid < 192) sWe1[tid] = We1[tid];
    if (tid < 64) {
        sbe1[tid] = be1[tid]; sbe2[tid] = be2[tid];
        sbm1[tid] = bm1[tid]; sbm2[tid] = bm2[tid];
    }
    __syncthreads();

    const int wid = tid >> 5, lane = tid & 31;
    const int grp = wid >> 3;                 // 0: edges 0-127, 1: edges 128-255
    const int cb = (wid & 7) * 8;             // channel base (8 channels)
    const int eb = grp * 128 + lane * 4;      // edge base (4 edges)

    for (int tile = blockIdx.x; tile < ntiles; tile += gridDim.x) {
        const int base = tile * TE;

        if (tid < TE) {
            int e = base + tid;
            int s = 0, d = -1;
            if (e < E) {
                if (idx64) { s = (int)ei64[e]; d = (int)ei64[(size_t)E + e]; }
                else       { s = ei32[e];      d = ei32[E + e]; }
                if (s < 0 || s >= N) s = 0;
                if (d < 0 || d >= N) d = 0;
            }
            sSrc[tid] = s;
            sDst[tid] = d;
        }
        __syncthreads();

        // delta = centroids[dst] - centroids[src]
        for (int i = tid; i < 3 * TE; i += TPB) {
            int e = i & (TE - 1), comp = i >> 8;
            int s = sSrc[e], d = sDst[e];
            int dd = (d < 0) ? s : d;
            sDelta[comp * AP + e] =
                cent[(size_t)dd * 3 + comp] - cent[(size_t)s * 3 + comp];
        }
        __syncthreads();

        ull acc[4][4];

        // L1: e1 = relu(delta @ We1 + be1) -> sA
        zero_acc(acc);
        gemmp(sDelta, AP, sWe1, 3, cb, eb, acc);
        store_relu(sA, acc, sbe1, cb, eb);
        GROUP_BAR(grp);

        // L2: e = relu(e1 @ We2 + be2) -> sB
        zero_acc(acc);
        gemmp(sA, AP, sWe2, 64, cb, eb, acc);
        store_relu(sB, acc, sbe2, cb, eb);
        GROUP_BAR(grp);

        // L3: m1 = relu(e @ Wm1c + P[src] + Q[dst] + bm1) -> sA
#pragma unroll
        for (int e = 0; e < 4; ++e) {
            int ed = eb + e;
            int s = sSrc[ed], d = sDst[ed];
            int dd = (d < 0) ? s : d;
            float4 p0 = *reinterpret_cast<const float4*>(&g_P[(size_t)s * 64 + cb]);
            float4 p1 = *reinterpret_cast<const float4*>(&g_P[(size_t)s * 64 + cb + 4]);
            float4 q0 = *reinterpret_cast<const float4*>(&g_Q[(size_t)dd * 64 + cb]);
            float4 q1 = *reinterpret_cast<const float4*>(&g_Q[(size_t)dd * 64 + cb + 4]);
            acc[0][e] = pack2(p0.x + q0.x, p0.y + q0.y);
            acc[1][e] = pack2(p0.z + q0.z, p0.w + q0.w);
            acc[2][e] = pack2(p1.x + q1.x, p1.y + q1.y);
            acc[3][e] = pack2(p1.z + q1.z, p1.w + q1.w);
        }
        gemmp(sB, AP, sWm1c, 64, cb, eb, acc);
        store_relu(sA, acc, sbm1, cb, eb);
        GROUP_BAR(grp);

        // L4: m = m1 @ Wm2 + bm2 -> scatter-add to sums[dst]
        zero_acc(acc);
        gemmp(sA, AP, sWm2, 64, cb, eb, acc);
#pragma unroll
        for (int e = 0; e < 4; ++e) {
            int d = sDst[eb + e];
            if (d >= 0) {
                float* p = &sums[(size_t)d * 64 + cb];
#pragma unroll
                for (int cp = 0; cp < 4; ++cp) {
                    float lo, hi;
                    unpack2(acc[cp][e], lo, hi);
                    atomicAdd(p + 2 * cp, lo + sbm2[cb + 2 * cp]);
                    atomicAdd(p + 2 * cp + 1, hi + sbm2[cb + 2 * cp + 1]);
                }
            }
        }
        if (tid < TE && sDst[tid] >= 0) atomicAdd(&g_cnt[sDst[tid]], 1.0f);
        __syncthreads();
    }
}

// ---- out_kernel: out = relu([z, sums/cnt] @ Wu1 + bu1) (in-place on sums) ----
// smem: sW 8192 | sb 64 | sZM 128*AP = 33280 -> 41536 floats
__global__ __launch_bounds__(TPB) void out_kernel(
    const float* __restrict__ z, const float* __restrict__ sums,
    const float* __restrict__ Wu1, const float* __restrict__ bu1,
    float* __restrict__ out, int N, int ntiles) {
    extern __shared__ float sm[];
    float* sW = sm;
    float* sb = sm + 8192;
    float* sZM = sm + 8256;

    const int tid = threadIdx.x;
    for (int i = tid; i < 8192; i += TPB) sW[i] = Wu1[i];
    if (tid < 64) sb[tid] = bu1[tid];
    __syncthreads();

    const int wid = tid >> 5, lane = tid & 31;
    const int grp = wid >> 3;
    const int cb = (wid & 7) * 8;
    const int eb = grp * 128 + lane * 4;

    for (int tile = blockIdx.x; tile < ntiles; tile += gridDim.x) {
        const int base = tile * TE;
        for (int i = tid; i < 128 * TE; i += TPB) {
            int nl = i >> 7, k = i & 127;
            int gn = base + nl;
            float v = 0.0f;
            if (gn < N) {
                if (k < 64) {
                    v = z[(size_t)gn * 64 + k];
                } else {
                    float c = fmaxf(g_cnt[gn], 1.0f);
                    v = sums[(size_t)gn * 64 + (k - 64)] / c;
                }
            }
            sZM[k * AP + nl] = v;
        }
        __syncthreads();

        ull acc[4][4];
        zero_acc(acc);
        gemmp(sZM, AP, sW, 128, cb, eb, acc);

#pragma unroll
        for (int e = 0; e < 4; ++e) {
            int gn = base + eb + e;
            if (gn < N) {
                float v[8];
#pragma unroll
                for (int cp = 0; cp < 4; ++cp)
                    unpack2(acc[cp][e], v[2 * cp], v[2 * cp + 1]);
                float4 o0, o1;
                o0.x = fmaxf(v[0] + sb[cb + 0], 0.0f);
                o0.y = fmaxf(v[1] + sb[cb + 1], 0.0f);
                o0.z = fmaxf(v[2] + sb[cb + 2], 0.0f);
                o0.w = fmaxf(v[3] + sb[cb + 3], 0.0f);
                o1.x = fmaxf(v[4] + sb[cb + 4], 0.0f);
                o1.y = fmaxf(v[5] + sb[cb + 5], 0.0f);
                o1.z = fmaxf(v[6] + sb[cb + 6], 0.0f);
                o1.w = fmaxf(v[7] + sb[cb + 7], 0.0f);
                *reinterpret_cast<float4*>(&out[(size_t)gn * 64 + cb]) = o0;
                *reinterpret_cast<float4*>(&out[(size_t)gn * 64 + cb + 4]) = o1;
            }
        }
        __syncthreads();
    }
}

extern "C" void kernel_launch(void* const* d_in, const int* in_sizes, int n_in,
                              void* d_out, int out_size) {
    const float* z    = (const float*)d_in[0];
    const float* cent = (const float*)d_in[1];
    const void* ei    = d_in[2];
    const float* We1 = (const float*)d_in[3];
    const float* be1 = (const float*)d_in[4];
    const float* We2 = (const float*)d_in[5];
    const float* be2 = (const float*)d_in[6];
    const float* Wm1 = (const float*)d_in[7];
    const float* bm1 = (const float*)d_in[8];
    const float* Wm2 = (const float*)d_in[9];
    const float* bm2 = (const float*)d_in[10];
    const float* Wu1 = (const float*)d_in[11];
    const float* bu1 = (const float*)d_in[12];
    float* out = (float*)d_out;

    const int N = in_sizes[0] / 64;
    const int E = in_sizes[2] / 2;
    const int ntiles_e = (E + TE - 1) / TE;
    const int ntiles_n = (N + TE - 1) / TE;

    const size_t smem_edge = 46796 * sizeof(float) + 2 * TE * sizeof(int);
    const size_t smem_pq   = 24832 * sizeof(float);
    const size_t smem_out  = 41536 * sizeof(float);

    cudaFuncSetAttribute(edge_kernel, cudaFuncAttributeMaxDynamicSharedMemorySize,
                         (int)smem_edge);
    cudaFuncSetAttribute(pq_kernel, cudaFuncAttributeMaxDynamicSharedMemorySize,
                         (int)smem_pq);
    cudaFuncSetAttribute(out_kernel, cudaFuncAttributeMaxDynamicSharedMemorySize,
                         (int)smem_out);

    detect_kernel<<<1, 32>>>((const unsigned long long*)ei);
    zero_kernel<<<(N * 64 + 255) / 256, 256>>>(out, N * 64, N);
    pq_kernel<<<ntiles_n, TPB, smem_pq>>>(z, Wm1, N, ntiles_n);
    edge_kernel<<<148, TPB, smem_edge>>>(cent, ei,
                                         We1, be1, We2, be2,
                                         Wm1, bm1, Wm2, bm2,
                                         out, E, N, ntiles_e);
    out_kernel<<<ntiles_n, TPB, smem_out>>>(z, out, Wu1, bu1, out, N, ntiles_n);
}